// round 1
// baseline (speedup 1.0000x reference)
#include <cuda_runtime.h>
#include <cstdint>

#define NTOK 8192
#define CDIM 1024
#define HDIM 4096
#define NEXP 8
#define NPAIR (NTOK * 2)

// ---------------- scratch (device globals; no allocs allowed) ----------------
__device__ float g_h[(size_t)NPAIR * HDIM];   // 268 MB: gelu(x@W1) per pair
__device__ float g_y[(size_t)NPAIR * CDIM];   // 67 MB: (h@W2) per pair
__device__ int   g_counts[NEXP];
__device__ int   g_cnt2[NEXP];
__device__ int   g_offsets[NEXP];
__device__ int   g_tope[NPAIR];               // per-token top2 expert ids
__device__ float g_topg[NPAIR];               // per-token top2 gates
__device__ int   g_pair_token[NPAIR];         // pair row -> token id
__device__ int   g_pair_of_token[NPAIR];      // token,slot -> pair row

// ---------------- helpers ----------------
__device__ __forceinline__ uint32_t f2tf32(float f) {
    uint32_t u;
    asm("cvt.rna.tf32.f32 %0, %1;" : "=r"(u) : "f"(f));
    return u;
}

__device__ __forceinline__ void mma_tf32(float4& c, const uint4& a, const uint2& b) {
    asm volatile(
        "mma.sync.aligned.m16n8k8.row.col.f32.tf32.tf32.f32 "
        "{%0,%1,%2,%3}, {%4,%5,%6,%7}, {%8,%9}, {%0,%1,%2,%3};"
        : "+f"(c.x), "+f"(c.y), "+f"(c.z), "+f"(c.w)
        : "r"(a.x), "r"(a.y), "r"(a.z), "r"(a.w), "r"(b.x), "r"(b.y));
}

__device__ __forceinline__ float gelu_tanh(float v) {
    // jax.nn.gelu default (approximate=True)
    float v3 = v * v * v;
    return 0.5f * v * (1.0f + tanhf(0.7978845608028654f * (v + 0.044715f * v3)));
}

// ---------------- small kernels ----------------
__global__ void zero_kernel() {
    int i = threadIdx.x;
    if (i < NEXP) { g_counts[i] = 0; g_cnt2[i] = 0; }
}

__global__ void router_kernel(const float* __restrict__ x, const float* __restrict__ Wr) {
    __shared__ float sW[CDIM * NEXP];  // 32KB
    int tid = threadIdx.x;
    for (int i = tid; i < CDIM * NEXP; i += 256) sW[i] = Wr[i];
    __syncthreads();

    int warp = tid >> 5, lane = tid & 31;
    int t = blockIdx.x * 8 + warp;
    const float* xr = x + (size_t)t * CDIM;

    float acc[NEXP];
#pragma unroll
    for (int e = 0; e < NEXP; e++) acc[e] = 0.0f;

    for (int i = lane; i < CDIM; i += 32) {
        float xv = xr[i];
#pragma unroll
        for (int e = 0; e < NEXP; e++) acc[e] += xv * sW[i * NEXP + e];
    }
#pragma unroll
    for (int off = 16; off > 0; off >>= 1) {
#pragma unroll
        for (int e = 0; e < NEXP; e++) acc[e] += __shfl_xor_sync(0xffffffffu, acc[e], off);
    }
    if (lane == 0) {
        float v0 = -3.4e38f, v1 = -3.4e38f;
        int e0 = 0, e1 = 0;
#pragma unroll
        for (int e = 0; e < NEXP; e++) {
            float v = acc[e];
            if (v > v0) { v1 = v0; e1 = e0; v0 = v; e0 = e; }
            else if (v > v1) { v1 = v; e1 = e; }
        }
        float x1 = expf(v1 - v0);
        float inv = 1.0f / (1.0f + x1);
        g_tope[2 * t] = e0;     g_tope[2 * t + 1] = e1;
        g_topg[2 * t] = inv;    g_topg[2 * t + 1] = x1 * inv;
        atomicAdd(&g_counts[e0], 1);
        atomicAdd(&g_counts[e1], 1);
    }
}

__global__ void offsets_kernel() {
    if (threadIdx.x == 0) {
        int off = 0;
        for (int e = 0; e < NEXP; e++) { g_offsets[e] = off; off += g_counts[e]; }
    }
}

__global__ void assign_kernel() {
    int t = blockIdx.x * 256 + threadIdx.x;
    if (t >= NTOK) return;
#pragma unroll
    for (int j = 0; j < 2; j++) {
        int e = g_tope[2 * t + j];
        int slot = atomicAdd(&g_cnt2[e], 1);
        int p = g_offsets[e] + slot;
        g_pair_token[p] = t;
        g_pair_of_token[2 * t + j] = p;
    }
}

// ---------------- grouped TF32 GEMM ----------------
// BM=128, BN=128, BK=16; 256 threads = 8 warps (4 along M x 2 along N)
// warp tile 32x64 -> 2 mSubs(16) x 8 nSubs(8), mma m16n8k8 tf32.
// Smem in "fragment layout" so mainloop fragments are one LDS.128 / LDS.64.
template <int KDIM, int NCOLS, bool GATHER, bool DOGELU>
__global__ __launch_bounds__(256) void moe_gemm(const float* __restrict__ A,
                                                const float* __restrict__ B,
                                                float* __restrict__ C) {
    int e = blockIdx.z;
    int cnt = g_counts[e];
    int mt = blockIdx.x;
    if (mt * 128 >= cnt) return;
    int off = g_offsets[e];
    int mrows = min(128, cnt - mt * 128);

    const float* Bb = B + (size_t)e * KDIM * NCOLS + (size_t)blockIdx.y * 128;

    int tid = threadIdx.x;
    // A row sources (2 rows per thread: tid/4 and tid/4+64), col group tid%4
    const float* aptr[2];
#pragma unroll
    for (int j = 0; j < 2; j++) {
        int r = (tid >> 2) + j * 64;
        if (r < mrows) {
            if (GATHER)
                aptr[j] = A + (size_t)g_pair_token[off + mt * 128 + r] * KDIM;
            else
                aptr[j] = A + (size_t)(off + mt * 128 + r) * KDIM;
        } else {
            aptr[j] = nullptr;
        }
    }
    int acg = tid & 3;          // A col group (k = acg*4 .. +3)
    int bk = tid >> 4;          // B row within tile (0..15)
    int bn = tid & 15;          // B col group base (n = (bn + j*16)*4)

    __shared__ uint32_t sA[2048];
    __shared__ uint32_t sB[2048];

    int warp = tid >> 5, lane = tid & 31;
    int wm = warp & 3, wn = warp >> 2;
    int mSubW = wm * 2, nSubW = wn * 8;

    float4 acc[2][8];
#pragma unroll
    for (int ms = 0; ms < 2; ms++)
#pragma unroll
        for (int ns = 0; ns < 8; ns++) acc[ms][ns] = make_float4(0.f, 0.f, 0.f, 0.f);

    float4 va[2], vb[2];
    const float4 zero4 = make_float4(0.f, 0.f, 0.f, 0.f);

#define LOAD_TILES(k0)                                                                 \
    {                                                                                  \
        _Pragma("unroll") for (int j = 0; j < 2; j++)                                  \
            va[j] = aptr[j] ? *(const float4*)(aptr[j] + (k0) + acg * 4) : zero4;      \
        _Pragma("unroll") for (int j = 0; j < 2; j++)                                  \
            vb[j] = *(const float4*)(Bb + (size_t)((k0) + bk) * NCOLS + (bn + j * 16) * 4); \
    }

#define STORE_TILES()                                                                  \
    {                                                                                  \
        _Pragma("unroll") for (int j = 0; j < 2; j++) {                                \
            int m = (tid >> 2) + j * 64;                                               \
            int mSub = m >> 4, r = m & 15;                                             \
            const float* fv = (const float*)&va[j];                                    \
            _Pragma("unroll") for (int q = 0; q < 4; q++) {                            \
                int k = acg * 4 + q;                                                   \
                int kSub = k >> 3, cc = k & 7;                                         \
                int lA = (r & 7) * 4 + (cc & 3);                                       \
                int rA = (r >> 3) + 2 * (cc >> 2);                                     \
                sA[(mSub * 2 + kSub) * 128 + lA * 4 + rA] = f2tf32(fv[q]);             \
            }                                                                          \
        }                                                                              \
        _Pragma("unroll") for (int j = 0; j < 2; j++) {                                \
            int kSub = bk >> 3, kk = bk & 7;                                           \
            const float* fv = (const float*)&vb[j];                                    \
            _Pragma("unroll") for (int q = 0; q < 4; q++) {                            \
                int nt = (bn + j * 16) * 4 + q;                                        \
                int nSub = nt >> 3, nn = nt & 7;                                       \
                int lB = nn * 4 + (kk & 3);                                            \
                int rB = kk >> 2;                                                      \
                sB[(kSub * 16 + nSub) * 64 + lB * 2 + rB] = f2tf32(fv[q]);             \
            }                                                                          \
        }                                                                              \
    }

    LOAD_TILES(0);
    STORE_TILES();
    __syncthreads();

    const int NIT = KDIM / 16;
    for (int kt = 0; kt < NIT; kt++) {
        if (kt + 1 < NIT) LOAD_TILES((kt + 1) * 16);
#pragma unroll
        for (int ks = 0; ks < 2; ks++) {
            uint4 af[2];
            uint2 bf[8];
#pragma unroll
            for (int ms = 0; ms < 2; ms++)
                af[ms] = *(const uint4*)&sA[((mSubW + ms) * 2 + ks) * 128 + lane * 4];
#pragma unroll
            for (int ns = 0; ns < 8; ns++)
                bf[ns] = *(const uint2*)&sB[(ks * 16 + nSubW + ns) * 64 + lane * 2];
#pragma unroll
            for (int ms = 0; ms < 2; ms++)
#pragma unroll
                for (int ns = 0; ns < 8; ns++) mma_tf32(acc[ms][ns], af[ms], bf[ns]);
        }
        __syncthreads();
        if (kt + 1 < NIT) {
            STORE_TILES();
            __syncthreads();
        }
    }

    // epilogue
    int r1 = lane >> 2;
    int cb = (lane & 3) * 2;
#pragma unroll
    for (int ms = 0; ms < 2; ms++) {
#pragma unroll
        for (int half = 0; half < 2; half++) {
            int lr = wm * 32 + ms * 16 + r1 + half * 8;
            if (lr < mrows) {
                size_t prow = (size_t)(off + mt * 128 + lr);
                float* dst = C + prow * NCOLS + (size_t)blockIdx.y * 128 + wn * 64;
#pragma unroll
                for (int ns = 0; ns < 8; ns++) {
                    float v0 = half ? acc[ms][ns].z : acc[ms][ns].x;
                    float v1 = half ? acc[ms][ns].w : acc[ms][ns].y;
                    if (DOGELU) { v0 = gelu_tanh(v0); v1 = gelu_tanh(v1); }
                    *(float2*)&dst[ns * 8 + cb] = make_float2(v0, v1);
                }
            }
        }
    }
#undef LOAD_TILES
#undef STORE_TILES
}

// ---------------- combine ----------------
__global__ void combine_kernel(float* __restrict__ out) {
    size_t idx = (size_t)blockIdx.x * 256 + threadIdx.x;  // float4 index
    int t = (int)(idx >> 8);
    int cg = (int)(idx & 255);
    int p0 = g_pair_of_token[2 * t];
    int p1 = g_pair_of_token[2 * t + 1];
    float g0 = g_topg[2 * t];
    float g1 = g_topg[2 * t + 1];
    float4 a = *(const float4*)&g_y[(size_t)p0 * CDIM + cg * 4];
    float4 b = *(const float4*)&g_y[(size_t)p1 * CDIM + cg * 4];
    float4 r;
    r.x = g0 * a.x + g1 * b.x;
    r.y = g0 * a.y + g1 * b.y;
    r.z = g0 * a.z + g1 * b.z;
    r.w = g0 * a.w + g1 * b.w;
    ((float4*)out)[idx] = r;
}

// ---------------- launch ----------------
extern "C" void kernel_launch(void* const* d_in, const int* in_sizes, int n_in,
                              void* d_out, int out_size) {
    const float* x  = (const float*)d_in[0];  // (8192, 1024)
    const float* Wr = (const float*)d_in[1];  // (1024, 8)
    const float* W1 = (const float*)d_in[2];  // (8, 1024, 4096)
    const float* W2 = (const float*)d_in[3];  // (8, 4096, 1024)
    float* out = (float*)d_out;

    float* h_ptr;  cudaGetSymbolAddress((void**)&h_ptr, g_h);
    float* y_ptr;  cudaGetSymbolAddress((void**)&y_ptr, g_y);

    zero_kernel<<<1, 32>>>();
    router_kernel<<<NTOK / 8, 256>>>(x, Wr);
    offsets_kernel<<<1, 32>>>();
    assign_kernel<<<NTOK / 256, 256>>>();
    moe_gemm<CDIM, HDIM, true, true><<<dim3(64, HDIM / 128, NEXP), 256>>>(x, W1, h_ptr);
    moe_gemm<HDIM, CDIM, false, false><<<dim3(64, CDIM / 128, NEXP), 256>>>(h_ptr, W2, y_ptr);
    combine_kernel<<<(NTOK * CDIM / 4) / 256, 256>>>(out);
}

// round 3
// speedup vs baseline: 1.0247x; 1.0247x over previous
#include <cuda_runtime.h>
#include <cstdint>

#define NTOK 8192
#define CDIM 1024
#define HDIM 4096
#define NEXP 8
#define NPAIR (NTOK * 2)
#define MAXTILES 160

// ---------------- scratch (device globals; no allocs allowed) ----------------
__device__ float g_h[(size_t)NPAIR * HDIM];   // gelu(x@W1) per pair
__device__ float g_y[(size_t)NPAIR * CDIM];   // (h@W2) per pair
__device__ int   g_counts[NEXP];
__device__ int   g_cnt2[NEXP];
__device__ int   g_offsets[NEXP];
__device__ int   g_tope[NPAIR];
__device__ float g_topg[NPAIR];
__device__ int   g_pair_token[NPAIR];
__device__ int   g_pair_of_token[NPAIR];
__device__ int   g_tile_e[MAXTILES];
__device__ int   g_tile_mt[MAXTILES];
__device__ int   g_total_tiles;

// ---------------- helpers ----------------
__device__ __forceinline__ uint32_t f2tf32(float f) {
    uint32_t u;
    asm("cvt.rna.tf32.f32 %0, %1;" : "=r"(u) : "f"(f));
    return u;
}

__device__ __forceinline__ void mma_tf32(float4& c, const uint4& a, const uint2& b) {
    asm volatile(
        "mma.sync.aligned.m16n8k8.row.col.f32.tf32.tf32.f32 "
        "{%0,%1,%2,%3}, {%4,%5,%6,%7}, {%8,%9}, {%0,%1,%2,%3};"
        : "+f"(c.x), "+f"(c.y), "+f"(c.z), "+f"(c.w)
        : "r"(a.x), "r"(a.y), "r"(a.z), "r"(a.w), "r"(b.x), "r"(b.y));
}

__device__ __forceinline__ float gelu_fast(float v) {
    // tanh-form gelu via sigmoid: v * sigmoid(2*0.79788456*(v + 0.044715 v^3))
    float z = 0.7978845608028654f * (v + 0.044715f * v * v * v);
    float t = __expf(-2.0f * z);
    return v / (1.0f + t);
}

// ---------------- small kernels ----------------
__global__ void zero_kernel() {
    int i = threadIdx.x;
    if (i < NEXP) { g_counts[i] = 0; g_cnt2[i] = 0; }
}

__global__ void router_kernel(const float* __restrict__ x, const float* __restrict__ Wr) {
    __shared__ float sW[CDIM * NEXP];
    int tid = threadIdx.x;
    for (int i = tid; i < CDIM * NEXP; i += 256) sW[i] = Wr[i];
    __syncthreads();

    int warp = tid >> 5, lane = tid & 31;
    int t = blockIdx.x * 8 + warp;
    const float* xr = x + (size_t)t * CDIM;

    float acc[NEXP];
#pragma unroll
    for (int e = 0; e < NEXP; e++) acc[e] = 0.0f;
    for (int i = lane; i < CDIM; i += 32) {
        float xv = xr[i];
#pragma unroll
        for (int e = 0; e < NEXP; e++) acc[e] += xv * sW[i * NEXP + e];
    }
#pragma unroll
    for (int off = 16; off > 0; off >>= 1)
#pragma unroll
        for (int e = 0; e < NEXP; e++) acc[e] += __shfl_xor_sync(0xffffffffu, acc[e], off);

    if (lane == 0) {
        float v0 = -3.4e38f, v1 = -3.4e38f;
        int e0 = 0, e1 = 0;
#pragma unroll
        for (int e = 0; e < NEXP; e++) {
            float v = acc[e];
            if (v > v0) { v1 = v0; e1 = e0; v0 = v; e0 = e; }
            else if (v > v1) { v1 = v; e1 = e; }
        }
        float x1 = expf(v1 - v0);
        float inv = 1.0f / (1.0f + x1);
        g_tope[2 * t] = e0;   g_tope[2 * t + 1] = e1;
        g_topg[2 * t] = inv;  g_topg[2 * t + 1] = x1 * inv;
        atomicAdd(&g_counts[e0], 1);
        atomicAdd(&g_counts[e1], 1);
    }
}

__global__ void offsets_tiles_kernel() {
    if (threadIdx.x == 0) {
        int off = 0, tt = 0;
        for (int e = 0; e < NEXP; e++) {
            g_offsets[e] = off;
            int cnt = g_counts[e];
            off += cnt;
            int mts = (cnt + 127) >> 7;
            for (int m = 0; m < mts; m++) { g_tile_e[tt] = e; g_tile_mt[tt] = m; tt++; }
        }
        g_total_tiles = tt;
    }
}

__global__ void assign_kernel() {
    int t = blockIdx.x * 256 + threadIdx.x;
    if (t >= NTOK) return;
#pragma unroll
    for (int j = 0; j < 2; j++) {
        int e = g_tope[2 * t + j];
        int slot = atomicAdd(&g_cnt2[e], 1);
        int p = g_offsets[e] + slot;
        g_pair_token[p] = t;
        g_pair_of_token[2 * t + j] = p;
    }
}

// ---------------- grouped TF32 GEMM (mma.sync, double-buffered) ----------------
// BM=128, BN=256, BK=16; 256 threads = 8 warps (2 along M x 4 along N)
// warp tile 64x64 -> 4 mSubs(16) x 8 nSubs(8), mma m16n8k8 tf32.
// Smem in fragment layout: mainloop fragments are one LDS.128 / LDS.64.
// Two smem stages, one __syncthreads per K-iteration.
template <int KDIM, int NCOLS, bool GATHER, bool DOGELU>
__global__ __launch_bounds__(256) void moe_gemm(const float* __restrict__ A,
                                                const float* __restrict__ B,
                                                float* __restrict__ C) {
    int ti = blockIdx.y;
    if (ti >= g_total_tiles) return;
    int e = g_tile_e[ti], mt = g_tile_mt[ti];
    int cnt = g_counts[e];
    int row0 = g_offsets[e] + mt * 128;
    int mrows = min(128, cnt - mt * 128);
    int n0 = blockIdx.x * 256;

    const float* Bb = B + (size_t)e * KDIM * NCOLS + n0;

    int tid = threadIdx.x;
    // A row sources (2 rows per thread: tid/4 and tid/4+64), col group tid%4
    const float* aptr[2];
#pragma unroll
    for (int j = 0; j < 2; j++) {
        int r = (tid >> 2) + j * 64;
        if (r < mrows) {
            if (GATHER)
                aptr[j] = A + (size_t)g_pair_token[row0 + r] * KDIM;
            else
                aptr[j] = A + (size_t)(row0 + r) * KDIM;
        } else {
            aptr[j] = nullptr;
        }
    }
    int acg = tid & 3;          // A col group (k = acg*4 .. +3)
    int bk = tid >> 4;          // B row within k-tile (0..15)
    int bq = tid & 15;          // B col float4 group base

    __shared__ uint32_t sA[2][2048];   // 16 KB
    __shared__ uint32_t sB[2][4096];   // 32 KB  (total 48 KB exactly)

    int warp = tid >> 5, lane = tid & 31;
    int wm = warp >> 2, wn = warp & 3;          // 2 x 4 warps
    int mSubW = wm * 4, nSubW = wn * 8;

    float4 acc[4][8];
#pragma unroll
    for (int ms = 0; ms < 4; ms++)
#pragma unroll
        for (int ns = 0; ns < 8; ns++) acc[ms][ns] = make_float4(0.f, 0.f, 0.f, 0.f);

    float4 va[2], vb[4];
    const float4 zero4 = make_float4(0.f, 0.f, 0.f, 0.f);

#define LOAD_TILES(k0)                                                                 \
    {                                                                                  \
        _Pragma("unroll") for (int j = 0; j < 2; j++)                                  \
            va[j] = aptr[j] ? *(const float4*)(aptr[j] + (k0) + acg * 4) : zero4;      \
        _Pragma("unroll") for (int j = 0; j < 4; j++)                                  \
            vb[j] = *(const float4*)(Bb + (size_t)((k0) + bk) * NCOLS + (bq + j * 16) * 4); \
    }

#define STORE_TILES(st)                                                                \
    {                                                                                  \
        _Pragma("unroll") for (int j = 0; j < 2; j++) {                                \
            int m = (tid >> 2) + j * 64;                                               \
            int mSub = m >> 4, r = m & 15;                                             \
            const float* fv = (const float*)&va[j];                                    \
            _Pragma("unroll") for (int q = 0; q < 4; q++) {                            \
                int k = acg * 4 + q;                                                   \
                int kSub = k >> 3, cc = k & 7;                                         \
                int lA = (r & 7) * 4 + (cc & 3);                                       \
                int rA = (r >> 3) + 2 * (cc >> 2);                                     \
                sA[st][(mSub * 2 + kSub) * 128 + lA * 4 + rA] = f2tf32(fv[q]);         \
            }                                                                          \
        }                                                                              \
        _Pragma("unroll") for (int j = 0; j < 4; j++) {                                \
            int kSub = bk >> 3, kk = bk & 7;                                           \
            const float* fv = (const float*)&vb[j];                                    \
            _Pragma("unroll") for (int q = 0; q < 4; q++) {                            \
                int nt = (bq + j * 16) * 4 + q;                                        \
                int nSub = nt >> 3, nn = nt & 7;                                       \
                int lB = nn * 4 + (kk & 3);                                            \
                int rB = kk >> 2;                                                      \
                sB[st][(kSub * 32 + nSub) * 64 + lB * 2 + rB] = f2tf32(fv[q]);         \
            }                                                                          \
        }                                                                              \
    }

    LOAD_TILES(0);
    STORE_TILES(0);
    __syncthreads();

    const int NIT = KDIM / 16;
    for (int kt = 0; kt < NIT; kt++) {
        int cur = kt & 1;
        if (kt + 1 < NIT) LOAD_TILES((kt + 1) * 16);
#pragma unroll
        for (int ks = 0; ks < 2; ks++) {
            uint4 af[4];
            uint2 bf[8];
#pragma unroll
            for (int ms = 0; ms < 4; ms++)
                af[ms] = *(const uint4*)&sA[cur][((mSubW + ms) * 2 + ks) * 128 + lane * 4];
#pragma unroll
            for (int ns = 0; ns < 8; ns++)
                bf[ns] = *(const uint2*)&sB[cur][(ks * 32 + nSubW + ns) * 64 + lane * 2];
#pragma unroll
            for (int ms = 0; ms < 4; ms++)
#pragma unroll
                for (int ns = 0; ns < 8; ns++) mma_tf32(acc[ms][ns], af[ms], bf[ns]);
        }
        if (kt + 1 < NIT) STORE_TILES((kt + 1) & 1);
        __syncthreads();
    }

    // epilogue
    int r1 = lane >> 2;
    int cb = (lane & 3) * 2;
#pragma unroll
    for (int ms = 0; ms < 4; ms++) {
#pragma unroll
        for (int half = 0; half < 2; half++) {
            int lr = wm * 64 + ms * 16 + r1 + half * 8;
            if (lr < mrows) {
                float* dst = C + (size_t)(row0 + lr) * NCOLS + n0 + wn * 64;
#pragma unroll
                for (int ns = 0; ns < 8; ns++) {
                    float v0 = half ? acc[ms][ns].z : acc[ms][ns].x;
                    float v1 = half ? acc[ms][ns].w : acc[ms][ns].y;
                    if (DOGELU) { v0 = gelu_fast(v0); v1 = gelu_fast(v1); }
                    *(float2*)&dst[ns * 8 + cb] = make_float2(v0, v1);
                }
            }
        }
    }
#undef LOAD_TILES
#undef STORE_TILES
}

// ---------------- combine ----------------
__global__ void combine_kernel(float* __restrict__ out) {
    size_t idx = (size_t)blockIdx.x * 256 + threadIdx.x;
    int t = (int)(idx >> 8);
    int cg = (int)(idx & 255);
    int p0 = g_pair_of_token[2 * t];
    int p1 = g_pair_of_token[2 * t + 1];
    float g0 = g_topg[2 * t], g1 = g_topg[2 * t + 1];
    float4 a = *(const float4*)&g_y[(size_t)p0 * CDIM + cg * 4];
    float4 b = *(const float4*)&g_y[(size_t)p1 * CDIM + cg * 4];
    float4 r;
    r.x = g0 * a.x + g1 * b.x;
    r.y = g0 * a.y + g1 * b.y;
    r.z = g0 * a.z + g1 * b.z;
    r.w = g0 * a.w + g1 * b.w;
    ((float4*)out)[idx] = r;
}

// ---------------- launch ----------------
extern "C" void kernel_launch(void* const* d_in, const int* in_sizes, int n_in,
                              void* d_out, int out_size) {
    const float* x  = (const float*)d_in[0];  // (8192, 1024)
    const float* Wr = (const float*)d_in[1];  // (1024, 8)
    const float* W1 = (const float*)d_in[2];  // (8, 1024, 4096)
    const float* W2 = (const float*)d_in[3];  // (8, 4096, 1024)
    float* out = (float*)d_out;

    float *h_ptr, *y_ptr;
    cudaGetSymbolAddress((void**)&h_ptr, g_h);
    cudaGetSymbolAddress((void**)&y_ptr, g_y);

    zero_kernel<<<1, 32>>>();
    router_kernel<<<NTOK / 8, 256>>>(x, Wr);
    offsets_tiles_kernel<<<1, 32>>>();
    assign_kernel<<<NTOK / 256, 256>>>();
    moe_gemm<CDIM, HDIM, true, true><<<dim3(HDIM / 256, 136), 256>>>(x, W1, h_ptr);
    moe_gemm<HDIM, CDIM, false, false><<<dim3(CDIM / 256, 136), 256>>>(h_ptr, W2, y_ptr);
    combine_kernel<<<(NTOK * CDIM / 4) / 256, 256>>>(out);
}

// round 4
// speedup vs baseline: 2.4463x; 2.3872x over previous
#include <cuda_runtime.h>
#include <cuda_fp16.h>
#include <cstdint>

#define NTOK 8192
#define CDIM 1024
#define HDIM 4096
#define NEXP 8
#define NPAIR (NTOK * 2)
#define MAXTILES 160

// ---------------- scratch (device globals; no allocs allowed) ----------------
__device__ __half g_h[(size_t)NPAIR * HDIM];  // gelu(x@W1), fp16, compacted pair rows
__device__ float  g_y[(size_t)NPAIR * CDIM];  // (h@W2) per pair
__device__ int    g_counts[NEXP];
__device__ int    g_cnt2[NEXP];
__device__ int    g_offsets[NEXP];
__device__ int    g_tope[NPAIR];
__device__ float  g_topg[NPAIR];
__device__ int    g_pair_token[NPAIR];
__device__ int    g_pair_of_token[NPAIR];
__device__ int    g_tile_e[MAXTILES];
__device__ int    g_tile_mt[MAXTILES];
__device__ int    g_total_tiles;

// ---------------- helpers ----------------
__device__ __forceinline__ uint32_t pk(float lo, float hi) {
    uint32_t u;
    asm("cvt.rn.f16x2.f32 %0, %1, %2;" : "=r"(u) : "f"(hi), "f"(lo));
    return u;
}

__device__ __forceinline__ uint32_t smem_u32(const void* p) {
    uint32_t a;
    asm("{ .reg .u64 t; cvta.to.shared.u64 t, %1; cvt.u32.u64 %0, t; }" : "=r"(a) : "l"(p));
    return a;
}

__device__ __forceinline__ void ldsm4(uint32_t* r, uint32_t addr) {
    asm volatile("ldmatrix.sync.aligned.m8n8.x4.shared.b16 {%0,%1,%2,%3}, [%4];"
                 : "=r"(r[0]), "=r"(r[1]), "=r"(r[2]), "=r"(r[3]) : "r"(addr));
}

__device__ __forceinline__ void ldsm4t(uint32_t* r, uint32_t addr) {
    asm volatile("ldmatrix.sync.aligned.m8n8.x4.trans.shared.b16 {%0,%1,%2,%3}, [%4];"
                 : "=r"(r[0]), "=r"(r[1]), "=r"(r[2]), "=r"(r[3]) : "r"(addr));
}

__device__ __forceinline__ void mma_f16(float4& c, const uint32_t* a, uint32_t b0, uint32_t b1) {
    asm volatile(
        "mma.sync.aligned.m16n8k16.row.col.f32.f16.f16.f32 "
        "{%0,%1,%2,%3}, {%4,%5,%6,%7}, {%8,%9}, {%0,%1,%2,%3};"
        : "+f"(c.x), "+f"(c.y), "+f"(c.z), "+f"(c.w)
        : "r"(a[0]), "r"(a[1]), "r"(a[2]), "r"(a[3]), "r"(b0), "r"(b1));
}

__device__ __forceinline__ float gelu_fast(float v) {
    // tanh-form gelu via sigmoid: v * sigmoid(2*0.79788456*(v + 0.044715 v^3))
    float z = 0.7978845608028654f * (v + 0.044715f * v * v * v);
    float t = __expf(-2.0f * z);
    return v / (1.0f + t);
}

// ---------------- small kernels ----------------
__global__ void zero_kernel() {
    int i = threadIdx.x;
    if (i < NEXP) { g_counts[i] = 0; g_cnt2[i] = 0; }
}

__global__ void router_kernel(const float* __restrict__ x, const float* __restrict__ Wr) {
    __shared__ float sW[CDIM * NEXP];
    int tid = threadIdx.x;
    for (int i = tid; i < CDIM * NEXP; i += 256) sW[i] = Wr[i];
    __syncthreads();

    int warp = tid >> 5, lane = tid & 31;
    int t = blockIdx.x * 8 + warp;
    const float* xr = x + (size_t)t * CDIM;

    float acc[NEXP];
#pragma unroll
    for (int e = 0; e < NEXP; e++) acc[e] = 0.0f;
    for (int i = lane; i < CDIM; i += 32) {
        float xv = xr[i];
#pragma unroll
        for (int e = 0; e < NEXP; e++) acc[e] += xv * sW[i * NEXP + e];
    }
#pragma unroll
    for (int off = 16; off > 0; off >>= 1)
#pragma unroll
        for (int e = 0; e < NEXP; e++) acc[e] += __shfl_xor_sync(0xffffffffu, acc[e], off);

    if (lane == 0) {
        float v0 = -3.4e38f, v1 = -3.4e38f;
        int e0 = 0, e1 = 0;
#pragma unroll
        for (int e = 0; e < NEXP; e++) {
            float v = acc[e];
            if (v > v0) { v1 = v0; e1 = e0; v0 = v; e0 = e; }
            else if (v > v1) { v1 = v; e1 = e; }
        }
        float x1 = expf(v1 - v0);
        float inv = 1.0f / (1.0f + x1);
        g_tope[2 * t] = e0;   g_tope[2 * t + 1] = e1;
        g_topg[2 * t] = inv;  g_topg[2 * t + 1] = x1 * inv;
        atomicAdd(&g_counts[e0], 1);
        atomicAdd(&g_counts[e1], 1);
    }
}

__global__ void offsets_tiles_kernel() {
    if (threadIdx.x == 0) {
        int off = 0, tt = 0;
        for (int e = 0; e < NEXP; e++) {
            g_offsets[e] = off;
            int cnt = g_counts[e];
            off += cnt;
            int mts = (cnt + 127) >> 7;
            for (int m = 0; m < mts; m++) { g_tile_e[tt] = e; g_tile_mt[tt] = m; tt++; }
        }
        g_total_tiles = tt;
    }
}

__global__ void assign_kernel() {
    int t = blockIdx.x * 256 + threadIdx.x;
    if (t >= NTOK) return;
#pragma unroll
    for (int j = 0; j < 2; j++) {
        int e = g_tope[2 * t + j];
        int slot = atomicAdd(&g_cnt2[e], 1);
        int p = g_offsets[e] + slot;
        g_pair_token[p] = t;
        g_pair_of_token[2 * t + j] = p;
    }
}

// ---------------- grouped fp16 GEMM (mma.sync.m16n8k16 + ldmatrix) ----------------
// BM=128, BN=256, BK=32. 256 threads = 8 warps (2 M x 4 N), warp tile 64x64.
// smem A: [128 rows][64B] fp16, chunk swizzle c2 ^= (r>>1)&3         (8KB/stage)
// smem B: [32 rows][512B] fp16, chunk swizzle cn ^= (k&7)^((k&1)<<2) (16KB/stage)
// Double buffered, one __syncthreads per K-iter. STS/LDSM verified conflict-free.
template <int KDIM, int NCOLS, bool IS_G1>
__global__ __launch_bounds__(256) void moe_gemm_h(const float* __restrict__ Af,
                                                  const __half* __restrict__ Ah,
                                                  const float* __restrict__ B,
                                                  __half* __restrict__ Ch,
                                                  float* __restrict__ Cf) {
    int ti = blockIdx.y;
    if (ti >= g_total_tiles) return;
    int e = g_tile_e[ti], mt = g_tile_mt[ti];
    int cnt = g_counts[e];
    int row0 = g_offsets[e] + mt * 128;
    int mrows = min(128, cnt - mt * 128);
    int n0 = blockIdx.x * 256;
    const float* Bb = B + (size_t)e * KDIM * NCOLS + n0;

    __shared__ __align__(128) uint8_t sm[49152];  // A: 2x8KB @0, B: 2x16KB @16384

    int tid = threadIdx.x, warp = tid >> 5, lane = tid & 31;

    // ---- A loader: thread t -> row ar=t>>1, two 16B chunks c2 = (t&1)*2 + {0,1}
    int ar = tid >> 1;
    bool aok = ar < mrows;
    const float* aRowF = nullptr;
    const __half* aRowH = nullptr;
    if (IS_G1) { if (aok) aRowF = Af + (size_t)g_pair_token[row0 + ar] * KDIM; }
    else       { if (aok) aRowH = Ah + (size_t)(row0 + ar) * KDIM; }
    int ac2 = (tid & 1) * 2;
    uint32_t aswz = (uint32_t)((ar >> 1) & 3);
    uint32_t aSts0 = ar * 64 + ((((uint32_t)ac2 + 0) ^ aswz) << 4);
    uint32_t aSts1 = ar * 64 + ((((uint32_t)ac2 + 1) ^ aswz) << 4);

    // ---- B loader: thread t -> k=t>>3, 8 float4 along n at (t&7)*4 + j*32
    int bk = tid >> 3, bv = tid & 7;
    uint32_t bex = (uint32_t)((bk & 7) ^ ((bk & 1) << 2));
    uint32_t bStsBase = bk * 512 + (tid & 1) * 8;

    // ---- ldmatrix addresses (stage-0 relative)
    int rloc = (lane & 7) + ((lane >> 3) & 1) * 8;
    int c2b = (lane >> 4) & 1;
    int wm = warp >> 2, wn = warp & 3;
    uint32_t aLd[4], bLd[4];
#pragma unroll
    for (int ms = 0; ms < 4; ms++) {
        int r = wm * 64 + ms * 16 + rloc;
        aLd[ms] = r * 64 + ((uint32_t)(c2b ^ ((r >> 1) & 3)) << 4);
    }
    uint32_t bex2 = (uint32_t)((rloc & 7) ^ ((rloc & 1) << 2));
#pragma unroll
    for (int p = 0; p < 4; p++) {
        uint32_t cn = (uint32_t)(wn * 8 + p * 2 + ((lane >> 4) & 1));
        bLd[p] = rloc * 512 + ((cn ^ bex2) << 4);
    }
    uint32_t smemBase = smem_u32(sm);

    float4 acc[4][8];
#pragma unroll
    for (int ms = 0; ms < 4; ms++)
#pragma unroll
        for (int ns = 0; ns < 8; ns++) acc[ms][ns] = make_float4(0.f, 0.f, 0.f, 0.f);

    uint32_t ast[8], bst[16];

#define LOADA(k0)                                                                      \
    {                                                                                  \
        if (IS_G1) {                                                                   \
            if (aok) {                                                                 \
                float4 f0 = *(const float4*)(aRowF + (k0) + ac2 * 8);                  \
                float4 f1 = *(const float4*)(aRowF + (k0) + ac2 * 8 + 4);              \
                float4 f2 = *(const float4*)(aRowF + (k0) + ac2 * 8 + 8);              \
                float4 f3 = *(const float4*)(aRowF + (k0) + ac2 * 8 + 12);             \
                ast[0] = pk(f0.x, f0.y); ast[1] = pk(f0.z, f0.w);                      \
                ast[2] = pk(f1.x, f1.y); ast[3] = pk(f1.z, f1.w);                      \
                ast[4] = pk(f2.x, f2.y); ast[5] = pk(f2.z, f2.w);                      \
                ast[6] = pk(f3.x, f3.y); ast[7] = pk(f3.z, f3.w);                      \
            } else {                                                                   \
                _Pragma("unroll") for (int q = 0; q < 8; q++) ast[q] = 0u;             \
            }                                                                          \
        } else {                                                                       \
            if (aok) {                                                                 \
                uint4 u0 = *(const uint4*)(aRowH + (k0) + ac2 * 8);                    \
                uint4 u1 = *(const uint4*)(aRowH + (k0) + ac2 * 8 + 8);                \
                ast[0] = u0.x; ast[1] = u0.y; ast[2] = u0.z; ast[3] = u0.w;            \
                ast[4] = u1.x; ast[5] = u1.y; ast[6] = u1.z; ast[7] = u1.w;            \
            } else {                                                                   \
                _Pragma("unroll") for (int q = 0; q < 8; q++) ast[q] = 0u;             \
            }                                                                          \
        }                                                                              \
    }

#define LOADB(k0)                                                                      \
    {                                                                                  \
        const float* bp = Bb + (size_t)((k0) + bk) * NCOLS + bv * 4;                   \
        _Pragma("unroll") for (int j = 0; j < 8; j++) {                                \
            float4 v = *(const float4*)(bp + j * 32);                                  \
            bst[2 * j] = pk(v.x, v.y);                                                 \
            bst[2 * j + 1] = pk(v.z, v.w);                                             \
        }                                                                              \
    }

#define STS(st)                                                                        \
    {                                                                                  \
        char* sa = (char*)sm + (st) * 8192;                                            \
        *(uint4*)(sa + aSts0) = make_uint4(ast[0], ast[1], ast[2], ast[3]);            \
        *(uint4*)(sa + aSts1) = make_uint4(ast[4], ast[5], ast[6], ast[7]);            \
        char* sb = (char*)sm + 16384 + (st) * 16384;                                   \
        _Pragma("unroll") for (int j = 0; j < 8; j++) {                                \
            uint32_t cn = (uint32_t)(bv >> 1) + 4u * j;                                \
            *(uint2*)(sb + bStsBase + ((cn ^ bex) << 4)) =                             \
                make_uint2(bst[2 * j], bst[2 * j + 1]);                                \
        }                                                                              \
    }

#define COMPUTE(st)                                                                    \
    {                                                                                  \
        uint32_t sa = smemBase + (st) * 8192;                                          \
        uint32_t sb = smemBase + 16384 + (st) * 16384;                                 \
        _Pragma("unroll") for (int ks = 0; ks < 2; ks++) {                             \
            uint32_t af[4][4], bf[4][4];                                               \
            _Pragma("unroll") for (int ms = 0; ms < 4; ms++)                           \
                ldsm4(af[ms], sa + (aLd[ms] ^ (ks << 5)));                             \
            _Pragma("unroll") for (int p = 0; p < 4; p++)                              \
                ldsm4t(bf[p], sb + bLd[p] + ks * 8192);                                \
            _Pragma("unroll") for (int ms = 0; ms < 4; ms++)                           \
                _Pragma("unroll") for (int p = 0; p < 4; p++) {                        \
                    mma_f16(acc[ms][2 * p], af[ms], bf[p][0], bf[p][1]);               \
                    mma_f16(acc[ms][2 * p + 1], af[ms], bf[p][2], bf[p][3]);           \
                }                                                                      \
        }                                                                              \
    }

    LOADA(0); LOADB(0);
    STS(0);
    __syncthreads();

    const int NIT = KDIM / 32;
    for (int kt = 0; kt < NIT; kt++) {
        if (kt + 1 < NIT) { LOADA((kt + 1) * 32); LOADB((kt + 1) * 32); }
        COMPUTE(kt & 1);
        if (kt + 1 < NIT) STS((kt + 1) & 1);
        __syncthreads();
    }

    // epilogue
    int r1 = lane >> 2, cb = (lane & 3) * 2;
#pragma unroll
    for (int ms = 0; ms < 4; ms++) {
#pragma unroll
        for (int half = 0; half < 2; half++) {
            int lr = wm * 64 + ms * 16 + r1 + half * 8;
            if (lr < mrows) {
                size_t rowoff = (size_t)(row0 + lr) * NCOLS + n0 + wn * 64;
#pragma unroll
                for (int ns = 0; ns < 8; ns++) {
                    float v0 = half ? acc[ms][ns].z : acc[ms][ns].x;
                    float v1 = half ? acc[ms][ns].w : acc[ms][ns].y;
                    if (IS_G1) {
                        v0 = gelu_fast(v0);
                        v1 = gelu_fast(v1);
                        uint32_t u = pk(v0, v1);
                        *(uint32_t*)(Ch + rowoff + ns * 8 + cb) = u;
                    } else {
                        *(float2*)(Cf + rowoff + ns * 8 + cb) = make_float2(v0, v1);
                    }
                }
            }
        }
    }
#undef LOADA
#undef LOADB
#undef STS
#undef COMPUTE
}

// ---------------- combine ----------------
__global__ void combine_kernel(float* __restrict__ out) {
    size_t idx = (size_t)blockIdx.x * 256 + threadIdx.x;
    int t = (int)(idx >> 8);
    int cg = (int)(idx & 255);
    int p0 = g_pair_of_token[2 * t];
    int p1 = g_pair_of_token[2 * t + 1];
    float g0 = g_topg[2 * t], g1 = g_topg[2 * t + 1];
    float4 a = *(const float4*)&g_y[(size_t)p0 * CDIM + cg * 4];
    float4 b = *(const float4*)&g_y[(size_t)p1 * CDIM + cg * 4];
    float4 r;
    r.x = g0 * a.x + g1 * b.x;
    r.y = g0 * a.y + g1 * b.y;
    r.z = g0 * a.z + g1 * b.z;
    r.w = g0 * a.w + g1 * b.w;
    ((float4*)out)[idx] = r;
}

// ---------------- launch ----------------
extern "C" void kernel_launch(void* const* d_in, const int* in_sizes, int n_in,
                              void* d_out, int out_size) {
    const float* x  = (const float*)d_in[0];  // (8192, 1024)
    const float* Wr = (const float*)d_in[1];  // (1024, 8)
    const float* W1 = (const float*)d_in[2];  // (8, 1024, 4096)
    const float* W2 = (const float*)d_in[3];  // (8, 4096, 1024)
    float* out = (float*)d_out;

    __half* h_ptr;
    float* y_ptr;
    cudaGetSymbolAddress((void**)&h_ptr, g_h);
    cudaGetSymbolAddress((void**)&y_ptr, g_y);

    zero_kernel<<<1, 32>>>();
    router_kernel<<<NTOK / 8, 256>>>(x, Wr);
    offsets_tiles_kernel<<<1, 32>>>();
    assign_kernel<<<NTOK / 256, 256>>>();
    moe_gemm_h<CDIM, HDIM, true><<<dim3(HDIM / 256, 136), 256>>>(x, nullptr, W1, h_ptr, nullptr);
    moe_gemm_h<HDIM, CDIM, false><<<dim3(CDIM / 256, 136), 256>>>(nullptr, h_ptr, W2, nullptr, y_ptr);
    combine_kernel<<<(NTOK * CDIM / 4) / 256, 256>>>(out);
}

// round 5
// speedup vs baseline: 4.4710x; 1.8276x over previous
#include <cuda_runtime.h>
#include <cuda_fp16.h>
#include <cstdint>

#define NTOK 8192
#define CDIM 1024
#define HDIM 4096
#define NEXP 8
#define NPAIR (NTOK * 2)
#define MAXTILES 160

// ---------------- scratch (device globals; no allocs allowed) ----------------
__device__ __half g_h[(size_t)(NPAIR + 128) * HDIM];   // gelu(x@W1), fp16 (padded rows)
__device__ float  g_y[(size_t)NPAIR * CDIM];           // (h@W2) per pair
__device__ __half g_xh[(size_t)(NPAIR + 128) * CDIM];  // gathered x rows, fp16 (padded)
__device__ __half g_w1h[(size_t)NEXP * CDIM * HDIM];   // W1 fp16
__device__ __half g_w2h[(size_t)NEXP * HDIM * CDIM];   // W2 fp16
__device__ int    g_counts[NEXP];
__device__ int    g_cnt2[NEXP];
__device__ int    g_offsets[NEXP];
__device__ int    g_tope[NPAIR];
__device__ float  g_topg[NPAIR];
__device__ int    g_pair_token[NPAIR];
__device__ int    g_pair_of_token[NPAIR];
__device__ int    g_tile_e[MAXTILES];
__device__ int    g_tile_mt[MAXTILES];
__device__ int    g_total_tiles;

// ---------------- helpers ----------------
__device__ __forceinline__ uint32_t pk(float lo, float hi) {
    uint32_t u;
    asm("cvt.rn.f16x2.f32 %0, %1, %2;" : "=r"(u) : "f"(hi), "f"(lo));
    return u;
}

__device__ __forceinline__ uint32_t smem_u32(const void* p) {
    uint32_t a;
    asm("{ .reg .u64 t; cvta.to.shared.u64 t, %1; cvt.u32.u64 %0, t; }" : "=r"(a) : "l"(p));
    return a;
}

__device__ __forceinline__ void cp16(uint32_t dst, const void* src) {
    asm volatile("cp.async.cg.shared.global [%0], [%1], 16;" :: "r"(dst), "l"(src));
}

__device__ __forceinline__ void ldsm4(uint32_t* r, uint32_t addr) {
    asm volatile("ldmatrix.sync.aligned.m8n8.x4.shared.b16 {%0,%1,%2,%3}, [%4];"
                 : "=r"(r[0]), "=r"(r[1]), "=r"(r[2]), "=r"(r[3]) : "r"(addr));
}

__device__ __forceinline__ void ldsm4t(uint32_t* r, uint32_t addr) {
    asm volatile("ldmatrix.sync.aligned.m8n8.x4.trans.shared.b16 {%0,%1,%2,%3}, [%4];"
                 : "=r"(r[0]), "=r"(r[1]), "=r"(r[2]), "=r"(r[3]) : "r"(addr));
}

__device__ __forceinline__ void mma_f16(float4& c, const uint32_t* a, uint32_t b0, uint32_t b1) {
    asm volatile(
        "mma.sync.aligned.m16n8k16.row.col.f32.f16.f16.f32 "
        "{%0,%1,%2,%3}, {%4,%5,%6,%7}, {%8,%9}, {%0,%1,%2,%3};"
        : "+f"(c.x), "+f"(c.y), "+f"(c.z), "+f"(c.w)
        : "r"(a[0]), "r"(a[1]), "r"(a[2]), "r"(a[3]), "r"(b0), "r"(b1));
}

__device__ __forceinline__ float gelu_fast(float v) {
    float z = 0.7978845608028654f * (v + 0.044715f * v * v * v);
    float t = __expf(-2.0f * z);
    return v / (1.0f + t);
}

// ---------------- small kernels ----------------
__global__ void zero_kernel() {
    int i = threadIdx.x;
    if (i < NEXP) { g_counts[i] = 0; g_cnt2[i] = 0; }
}

__global__ void router_kernel(const float* __restrict__ x, const float* __restrict__ Wr) {
    __shared__ float sW[CDIM * NEXP];
    int tid = threadIdx.x;
    for (int i = tid; i < CDIM * NEXP; i += 256) sW[i] = Wr[i];
    __syncthreads();

    int warp = tid >> 5, lane = tid & 31;
    int t = blockIdx.x * 8 + warp;
    const float* xr = x + (size_t)t * CDIM;

    float acc[NEXP];
#pragma unroll
    for (int e = 0; e < NEXP; e++) acc[e] = 0.0f;
    for (int i = lane; i < CDIM; i += 32) {
        float xv = xr[i];
#pragma unroll
        for (int e = 0; e < NEXP; e++) acc[e] += xv * sW[i * NEXP + e];
    }
#pragma unroll
    for (int off = 16; off > 0; off >>= 1)
#pragma unroll
        for (int e = 0; e < NEXP; e++) acc[e] += __shfl_xor_sync(0xffffffffu, acc[e], off);

    if (lane == 0) {
        float v0 = -3.4e38f, v1 = -3.4e38f;
        int e0 = 0, e1 = 0;
#pragma unroll
        for (int e = 0; e < NEXP; e++) {
            float v = acc[e];
            if (v > v0) { v1 = v0; e1 = e0; v0 = v; e0 = e; }
            else if (v > v1) { v1 = v; e1 = e; }
        }
        float x1 = expf(v1 - v0);
        float inv = 1.0f / (1.0f + x1);
        g_tope[2 * t] = e0;   g_tope[2 * t + 1] = e1;
        g_topg[2 * t] = inv;  g_topg[2 * t + 1] = x1 * inv;
        atomicAdd(&g_counts[e0], 1);
        atomicAdd(&g_counts[e1], 1);
    }
}

__global__ void offsets_tiles_kernel() {
    if (threadIdx.x == 0) {
        int off = 0, tt = 0;
        for (int e = 0; e < NEXP; e++) {
            g_offsets[e] = off;
            int cnt = g_counts[e];
            off += cnt;
            int mts = (cnt + 127) >> 7;
            for (int m = 0; m < mts; m++) { g_tile_e[tt] = e; g_tile_mt[tt] = m; tt++; }
        }
        g_total_tiles = tt;
    }
}

__global__ void assign_kernel() {
    int t = blockIdx.x * 256 + threadIdx.x;
    if (t >= NTOK) return;
#pragma unroll
    for (int j = 0; j < 2; j++) {
        int e = g_tope[2 * t + j];
        int slot = atomicAdd(&g_cnt2[e], 1);
        int p = g_offsets[e] + slot;
        g_pair_token[p] = t;
        g_pair_of_token[2 * t + j] = p;
    }
}

// fp32 -> fp16 bulk convert (grid-stride over float4)
__global__ void f2h_kernel(const float* __restrict__ src, __half* __restrict__ dst, int n4) {
    int i = blockIdx.x * 256 + threadIdx.x;
    if (i >= n4) return;
    float4 v = ((const float4*)src)[i];
    uint2 u;
    u.x = pk(v.x, v.y);
    u.y = pk(v.z, v.w);
    ((uint2*)dst)[i] = u;
}

// gather x rows into compacted pair order as fp16
__global__ void gather_xh_kernel(const float* __restrict__ x) {
    int p = blockIdx.x;
    int t = g_pair_token[p];
    const float4* src = (const float4*)(x + (size_t)t * CDIM);
    uint4* dst = (uint4*)(g_xh + (size_t)p * CDIM);
    int i = threadIdx.x;  // 128 threads, 8 elems each
    float4 a = src[2 * i], b = src[2 * i + 1];
    dst[i] = make_uint4(pk(a.x, a.y), pk(a.z, a.w), pk(b.x, b.y), pk(b.z, b.w));
}

// ---------------- grouped fp16 GEMM: cp.async 4-stage + mma.sync ----------------
// BM=128, BN=128, BK=32. 256 threads = 8 warps (2 M x 4 N), warp tile 64x32.
// smem/stage 16KB (A 8KB + B 8KB), 4 stages = 64KB dyn smem, 2 CTAs/SM.
// A swizzle: chunk c2 ^= (r>>1)&3 (64B rows). B swizzle: cn ^= (k&7)^((k&1)<<2) (256B rows).
#define GSTAGES 4
#define STG_BYTES 16384
#define DYN_SMEM (GSTAGES * STG_BYTES)

template <int KDIM, int NCOLS, bool DOGELU>
__global__ __launch_bounds__(256, 2) void moe_gemm_cp(const __half* __restrict__ A,
                                                      const __half* __restrict__ B,
                                                      __half* __restrict__ Ch,
                                                      float* __restrict__ Cf) {
    int ti = blockIdx.y;
    if (ti >= g_total_tiles) return;
    int e = g_tile_e[ti], mt = g_tile_mt[ti];
    int cnt = g_counts[e];
    int row0 = g_offsets[e] + mt * 128;
    int mrows = min(128, cnt - mt * 128);
    int n0 = blockIdx.x * 128;
    const __half* Bb = B + (size_t)e * KDIM * NCOLS + n0;

    extern __shared__ __align__(128) uint8_t sm[];
    uint32_t smemBase = smem_u32(sm);

    int tid = threadIdx.x, warp = tid >> 5, lane = tid & 31;
    int wm = warp >> 2, wn = warp & 3;

    // A loader: thread t -> row ar = t>>1, chunks c2base = (t&1)*2 + {0,1}
    int ar = tid >> 1;
    int ac2 = (tid & 1) * 2;
    uint32_t aswz = (uint32_t)((ar >> 1) & 3);
    const __half* aSrc = A + (size_t)(row0 + ar) * KDIM + ac2 * 8;
    uint32_t aD0 = ar * 64 + ((((uint32_t)ac2 + 0) ^ aswz) << 4);
    uint32_t aD1 = ar * 64 + ((((uint32_t)ac2 + 1) ^ aswz) << 4);

    // B loader: thread t -> row bk = t>>3, chunks cnbase = (t&7)*2 + {0,1}
    int bk = tid >> 3;
    int bcn = (tid & 7) * 2;
    uint32_t bex = (uint32_t)((bk & 7) ^ ((bk & 1) << 2));
    const __half* bSrc = Bb + (size_t)bk * NCOLS + bcn * 8;
    uint32_t bD0 = 8192 + bk * 256 + ((((uint32_t)bcn + 0) ^ bex) << 4);
    uint32_t bD1 = 8192 + bk * 256 + ((((uint32_t)bcn + 1) ^ bex) << 4);

    // ldmatrix addresses (stage-relative)
    int rloc = (lane & 7) + ((lane >> 3) & 1) * 8;
    int c2b = (lane >> 4) & 1;
    uint32_t aLd[4], bLd[2];
#pragma unroll
    for (int ms = 0; ms < 4; ms++) {
        int r = wm * 64 + ms * 16 + rloc;
        aLd[ms] = r * 64 + ((uint32_t)(c2b ^ ((r >> 1) & 3)) << 4);
    }
    uint32_t bex2 = (uint32_t)((rloc & 7) ^ ((rloc & 1) << 2));
#pragma unroll
    for (int p = 0; p < 2; p++) {
        uint32_t cn = (uint32_t)(wn * 4 + p * 2 + c2b);
        bLd[p] = 8192 + rloc * 256 + ((cn ^ bex2) << 4);
    }

    float4 acc[4][4];
#pragma unroll
    for (int ms = 0; ms < 4; ms++)
#pragma unroll
        for (int ns = 0; ns < 4; ns++) acc[ms][ns] = make_float4(0.f, 0.f, 0.f, 0.f);

#define ISSUE(k0, st)                                                                  \
    {                                                                                  \
        uint32_t sb = smemBase + (st) * STG_BYTES;                                     \
        cp16(sb + aD0, aSrc + (k0));                                                   \
        cp16(sb + aD1, aSrc + (k0) + 8);                                               \
        cp16(sb + bD0, bSrc + (size_t)(k0) * NCOLS);                                   \
        cp16(sb + bD1, bSrc + (size_t)(k0) * NCOLS + 8);                               \
        asm volatile("cp.async.commit_group;" ::: "memory");                           \
    }

#define COMPUTE(st)                                                                    \
    {                                                                                  \
        uint32_t sb = smemBase + (st) * STG_BYTES;                                     \
        _Pragma("unroll") for (int ks = 0; ks < 2; ks++) {                             \
            uint32_t af[4][4], bf[2][4];                                               \
            _Pragma("unroll") for (int ms = 0; ms < 4; ms++)                           \
                ldsm4(af[ms], sb + (aLd[ms] ^ (ks << 5)));                             \
            _Pragma("unroll") for (int p = 0; p < 2; p++)                              \
                ldsm4t(bf[p], sb + bLd[p] + ks * 4096);                                \
            _Pragma("unroll") for (int ms = 0; ms < 4; ms++)                           \
                _Pragma("unroll") for (int p = 0; p < 2; p++) {                        \
                    mma_f16(acc[ms][2 * p], af[ms], bf[p][0], bf[p][1]);               \
                    mma_f16(acc[ms][2 * p + 1], af[ms], bf[p][2], bf[p][3]);           \
                }                                                                      \
        }                                                                              \
    }

    const int NIT = KDIM / 32;
    ISSUE(0, 0);
    ISSUE(32, 1);
    ISSUE(64, 2);
    int kIss = 3;

    for (int kt = 0; kt < NIT; kt++) {
        asm volatile("cp.async.wait_group 2;" ::: "memory");
        __syncthreads();
        if (kIss < NIT) { ISSUE(kIss * 32, kIss & 3); kIss++; }
        COMPUTE(kt & 3);
    }

    // epilogue: warp covers rows wm*64..+63, cols n0 + wn*32..+31
    int r1 = lane >> 2, cb = (lane & 3) * 2;
#pragma unroll
    for (int ms = 0; ms < 4; ms++) {
#pragma unroll
        for (int half = 0; half < 2; half++) {
            int lr = wm * 64 + ms * 16 + r1 + half * 8;
            if (lr < mrows) {
                size_t rowoff = (size_t)(row0 + lr) * NCOLS + n0 + wn * 32;
#pragma unroll
                for (int ns = 0; ns < 4; ns++) {
                    float v0 = half ? acc[ms][ns].z : acc[ms][ns].x;
                    float v1 = half ? acc[ms][ns].w : acc[ms][ns].y;
                    if (DOGELU) {
                        v0 = gelu_fast(v0);
                        v1 = gelu_fast(v1);
                        *(uint32_t*)(Ch + rowoff + ns * 8 + cb) = pk(v0, v1);
                    } else {
                        *(float2*)(Cf + rowoff + ns * 8 + cb) = make_float2(v0, v1);
                    }
                }
            }
        }
    }
#undef ISSUE
#undef COMPUTE
}

// ---------------- combine ----------------
__global__ void combine_kernel(float* __restrict__ out) {
    size_t idx = (size_t)blockIdx.x * 256 + threadIdx.x;
    int t = (int)(idx >> 8);
    int cg = (int)(idx & 255);
    int p0 = g_pair_of_token[2 * t];
    int p1 = g_pair_of_token[2 * t + 1];
    float g0 = g_topg[2 * t], g1 = g_topg[2 * t + 1];
    float4 a = *(const float4*)&g_y[(size_t)p0 * CDIM + cg * 4];
    float4 b = *(const float4*)&g_y[(size_t)p1 * CDIM + cg * 4];
    float4 r;
    r.x = g0 * a.x + g1 * b.x;
    r.y = g0 * a.y + g1 * b.y;
    r.z = g0 * a.z + g1 * b.z;
    r.w = g0 * a.w + g1 * b.w;
    ((float4*)out)[idx] = r;
}

// ---------------- launch ----------------
extern "C" void kernel_launch(void* const* d_in, const int* in_sizes, int n_in,
                              void* d_out, int out_size) {
    const float* x  = (const float*)d_in[0];  // (8192, 1024)
    const float* Wr = (const float*)d_in[1];  // (1024, 8)
    const float* W1 = (const float*)d_in[2];  // (8, 1024, 4096)
    const float* W2 = (const float*)d_in[3];  // (8, 4096, 1024)
    float* out = (float*)d_out;

    __half *h_ptr, *xh_ptr, *w1h_ptr, *w2h_ptr;
    float* y_ptr;
    cudaGetSymbolAddress((void**)&h_ptr, g_h);
    cudaGetSymbolAddress((void**)&y_ptr, g_y);
    cudaGetSymbolAddress((void**)&xh_ptr, g_xh);
    cudaGetSymbolAddress((void**)&w1h_ptr, g_w1h);
    cudaGetSymbolAddress((void**)&w2h_ptr, g_w2h);

    cudaFuncSetAttribute(moe_gemm_cp<CDIM, HDIM, true>,
                         cudaFuncAttributeMaxDynamicSharedMemorySize, DYN_SMEM);
    cudaFuncSetAttribute(moe_gemm_cp<HDIM, CDIM, false>,
                         cudaFuncAttributeMaxDynamicSharedMemorySize, DYN_SMEM);

    const int WELEM4 = NEXP * CDIM * HDIM / 4;

    zero_kernel<<<1, 32>>>();
    router_kernel<<<NTOK / 8, 256>>>(x, Wr);
    offsets_tiles_kernel<<<1, 32>>>();
    assign_kernel<<<NTOK / 256, 256>>>();
    gather_xh_kernel<<<NPAIR, 128>>>(x);
    f2h_kernel<<<(WELEM4 + 255) / 256, 256>>>(W1, w1h_ptr, WELEM4);
    f2h_kernel<<<(WELEM4 + 255) / 256, 256>>>(W2, w2h_ptr, WELEM4);
    moe_gemm_cp<CDIM, HDIM, true><<<dim3(HDIM / 128, 136), 256, DYN_SMEM>>>(xh_ptr, w1h_ptr, h_ptr, nullptr);
    moe_gemm_cp<HDIM, CDIM, false><<<dim3(CDIM / 128, 136), 256, DYN_SMEM>>>(h_ptr, w2h_ptr, nullptr, y_ptr);
    combine_kernel<<<(NTOK * CDIM / 4) / 256, 256>>>(out);
}